// round 8
// baseline (speedup 1.0000x reference)
#include <cuda_runtime.h>
#include <cstdint>

#define N_QUBITS 16
#define DIM 65536
#define BATCH 128

// Scratch state buffers (device globals: allocation-free rule).
__device__ __align__(16) float4 g_state0[BATCH * DIM / 2];
__device__ __align__(16) float4 g_state1[BATCH * DIM / 2];
__device__ float g_partial[BATCH * 16 * 16];   // [b][loGroup][q]

// Precomputed per-(batch,layer) gate data (filled in k_init's prep phase).
__device__ float2 g_cs  [BATCH * 4 * 16];          // rotation (c,s) per bit p
__device__ float2 g_TLt [BATCH * 4 * 2 * 256];     // TL[b8][lo]
__device__ float2 g_THt [BATCH * 4 * 256 * 2];     // TH[hi][b0]

// ---------------------------------------------------------------------------
__device__ __forceinline__ float2 cmul(float2 a, float2 b) {
    return make_float2(a.x * b.x - a.y * b.y, a.x * b.y + a.y * b.x);
}
// bit ? conj(v) : v
__device__ __forceinline__ float2 sel(float2 v, int bit) {
    return bit ? make_float2(v.x, -v.y) : v;
}

// CNOT-ring permutation sigma (GF(2)-linear): j_p = XOR(i_p..i_15) p<=14,
// j_15 = XOR(i_0..i_14).
__device__ __forceinline__ int sigma16(int i) {
    int t = i;
    t ^= t >> 1; t ^= t >> 2; t ^= t >> 4; t ^= t >> 8;
    int b15 = (t ^ (i >> 15)) & 1;
    return (t & 0x7FFF) | (b15 << 15);
}

// ---------------------------------------------------------------------------
// First column of G = Rot(phi,theta,omega) @ RY(x): a=G00=(g0,g1), b=G10=(g4,g5).
__device__ void gate_col(const float* __restrict__ x,
                         const float* __restrict__ w,
                         int b, int l, int q,
                         float& g0, float& g1, float& g4, float& g5) {
    float xv  = x[(b * 4 + l) * 16 + q];
    const float* wp = w + (l * 16 + q) * 3;
    float phi = wp[0], th = wp[1], om = wp[2];
    float ct, st, cr, sr, sp, cp, sm, cm;
    sincosf(0.5f * th, &st, &ct);
    sincosf(0.5f * xv, &sr, &cr);
    sincosf(0.5f * (phi + om), &sp, &cp);
    sincosf(0.5f * (phi - om), &sm, &cm);
    float m00r =  cp * ct, m00i = -sp * ct;
    float m01r = -cm * st, m01i = -sm * st;
    float m10r =  cm * st, m10i = -sm * st;
    float m11r =  cp * ct, m11i =  sp * ct;
    g0 = m00r * cr + m01r * sr;  g1 = m00i * cr + m01i * sr;
    g4 = m10r * cr + m11r * sr;  g5 = m10i * cr + m11i * sr;
}

// G = diag(p0,conj p0) @ [[c,-s],[s,c]] @ diag(q0,conj q0)
__device__ void gate_decomp(const float* __restrict__ x,
                            const float* __restrict__ w,
                            int b, int l, int q,
                            float2& cs, float2& q0, float2& p0) {
    float g0, g1, g4, g5;
    gate_col(x, w, b, l, q, g0, g1, g4, g5);
    float ca = sqrtf(g0 * g0 + g1 * g1);
    float sb = sqrtf(g4 * g4 + g5 * g5);
    float au = atan2f(g1, g0);
    float av = atan2f(g5, g4);
    float s1, c1, s2, c2;
    sincosf(0.5f * (au + av), &s1, &c1);
    sincosf(0.5f * (au - av), &s2, &c2);
    cs = make_float2(ca, sb);
    q0 = make_float2(c1, s1);
    p0 = make_float2(c2, s2);
}

// ---------------------------------------------------------------------------
// Real butterfly network on 8 float2 amps (used by k_high):
//   lane bits 0..4 -> gcs[0..4] (shfl), reg bits -> gcs[5..7].
__device__ __forceinline__ void apply8_real(float2 v[8],
                                            const float2* __restrict__ gcs,
                                            int lane) {
    #pragma unroll
    for (int pb = 0; pb < 3; pb++) {
        int m = 1 << pb;
        float2 cp = gcs[5 + pb];
        float c = cp.x, s = cp.y;
        #pragma unroll
        for (int r = 0; r < 8; r++)
            if (!(r & m)) {
                float2 A = v[r], B = v[r + m];
                v[r]     = make_float2(c * A.x - s * B.x, c * A.y - s * B.y);
                v[r + m] = make_float2(s * A.x + c * B.x, s * A.y + c * B.y);
            }
    }
    #pragma unroll
    for (int p = 0; p < 5; p++) {
        float2 cp = gcs[p];
        float c = cp.x;
        float s = ((lane >> p) & 1) ? cp.y : -cp.y;
        #pragma unroll
        for (int r = 0; r < 8; r++) {
            float px = __shfl_xor_sync(0xffffffffu, v[r].x, 1 << p);
            float py = __shfl_xor_sync(0xffffffffu, v[r].y, 1 << p);
            v[r].x = c * v[r].x + s * px;
            v[r].y = c * v[r].y + s * py;
        }
    }
}

// ---------------------------------------------------------------------------
// K1 (merged prep + init). Prep: gate decompositions + diagonal tables for
// layers 1..3. Init: layer-0 product state written in the sigma-permuted domain.
__global__ __launch_bounds__(256)
void k_init(const float* __restrict__ x, const float* __restrict__ w,
            float4* __restrict__ st4) {
    int b = blockIdx.x, tid = threadIdx.x;

    // ---- prep phase ----
    __shared__ float2 sq0[3][16], sp0[3][16], sid[16];
    if (tid < 48) {
        int l = tid >> 4, p = tid & 15;        // layer l+1; bit p -> qubit 15-p
        float2 cs, q0, p0;
        gate_decomp(x, w, b, l + 1, 15 - p, cs, q0, p0);
        sq0[l][p] = q0; sp0[l][p] = p0;
        g_cs[(b * 4 + l + 1) * 16 + p] = cs;
    }
    if (tid < 16) sid[tid] = make_float2(1.f, 0.f);
    __syncthreads();

    #pragma unroll
    for (int li = 0; li < 3; li++) {           // layer = li+1
        const float2* q2 = sq0[li];
        const float2* p1 = (li == 0) ? sid : sp0[li - 1];
        int base = (b * 4 + li + 1);
        {   // TL(lo=m, b8)
            int m = tid;
            float2 acc = sel(q2[0], m & 1);
            #pragma unroll
            for (int p = 1; p <= 7; p++) acc = cmul(acc, sel(q2[p], (m >> p) & 1));
            #pragma unroll
            for (int p = 0; p <= 6; p++)
                acc = cmul(acc, sel(p1[p], ((m >> p) ^ (m >> (p + 1))) & 1));
            int m7 = (m >> 7) & 1;
            g_TLt[(base * 2 + 0) * 256 + m] = cmul(acc, sel(p1[7], m7));
            g_TLt[(base * 2 + 1) * 256 + m] = cmul(acc, sel(p1[7], m7 ^ 1));
        }
        {   // TH(hi, b0)
            int hi = tid;
            float2 acc = sel(q2[8], hi & 1);
            #pragma unroll
            for (int p = 9; p <= 15; p++)
                acc = cmul(acc, sel(q2[p], (hi >> (p - 8)) & 1));
            #pragma unroll
            for (int p = 8; p <= 13; p++)
                acc = cmul(acc, sel(p1[p], ((hi >> (p - 8)) ^ (hi >> (p - 7))) & 1));
            int h6 = (hi >> 6) & 1, h7 = (hi >> 7) & 1;
            #pragma unroll
            for (int b0 = 0; b0 < 2; b0++) {
                float2 a2 = cmul(acc, sel(p1[14], h6 ^ b0 ^ h7));
                a2 = cmul(a2, sel(p1[15], b0 ^ h7));
                g_THt[(base * 256 + hi) * 2 + b0] = a2;
            }
        }
    }

    // ---- init phase ----
    __shared__ float2 colA[16][2];
    __shared__ __align__(16) float2 AL[2][256];
    __shared__ float2 AH[2][256];
    if (tid < 16) {
        float g0, g1, g4, g5;
        gate_col(x, w, b, 0, 15 - tid, g0, g1, g4, g5);
        colA[tid][0] = make_float2(g0, g1);
        colA[tid][1] = make_float2(g4, g5);
    }
    __syncthreads();
    {
        int m = tid;
        float2 acc = colA[0][(m ^ (m >> 1)) & 1];
        #pragma unroll
        for (int p = 1; p <= 6; p++)
            acc = cmul(acc, colA[p][((m >> p) ^ (m >> (p + 1))) & 1]);
        int m7 = (m >> 7) & 1;
        AL[0][m] = cmul(acc, colA[7][m7]);
        AL[1][m] = cmul(acc, colA[7][m7 ^ 1]);
    }
    {
        int m = tid;
        float2 acc = colA[8][(m ^ (m >> 1)) & 1];
        #pragma unroll
        for (int p = 9; p <= 13; p++)
            acc = cmul(acc, colA[p][((m >> (p - 8)) ^ (m >> (p - 7))) & 1]);
        int h6 = (m >> 6) & 1, h7 = (m >> 7) & 1;
        AH[0][m] = cmul(acc, cmul(colA[14][h6 ^ h7],     colA[15][h7]));
        AH[1][m] = cmul(acc, cmul(colA[14][h6 ^ 1 ^ h7], colA[15][1 ^ h7]));
    }
    __syncthreads();
    float4* base = st4 + (size_t)b * (DIM / 2);
    #pragma unroll 4
    for (int it = 0; it < 128; it++) {
        int j0 = it * 512 + tid * 2;
        int lo = j0 & 255, hi = j0 >> 8;
        const float2* ALs = AL[hi & 1];
        float2 a0 = cmul(AH[0][hi], ALs[lo]);
        float2 a1 = cmul(AH[1][hi], ALs[lo + 1]);
        base[it * 256 + tid] = make_float4(a0.x, a0.y, a1.x, a1.y);
    }
}

// ---------------------------------------------------------------------------
// KA: combined diagonal (precomputed TL/TH tables) + real rotations on
// j-bits 0..7. float4 I/O (bit0 intra-register).
__global__ __launch_bounds__(256)
void k_low(int layer, float4* __restrict__ st4) {
    int b = blockIdx.y, tid = threadIdx.x;
    int wid = tid >> 5, lane = tid & 31;
    __shared__ float2 gcs[8];
    __shared__ __align__(16) float2 TL[2][256];
    __shared__ float2 THs[8][2];

    int base = b * 4 + layer;
    if (tid < 8) gcs[tid] = g_cs[base * 16 + tid];
    TL[0][tid] = g_TLt[(base * 2 + 0) * 256 + tid];
    TL[1][tid] = g_TLt[(base * 2 + 1) * 256 + tid];
    if (tid < 16) {
        int wi = tid >> 1, b0 = tid & 1;
        int hig = blockIdx.x * 8 + wi;
        THs[wi][b0] = g_THt[(base * 256 + hig) * 2 + b0];
    }
    __syncthreads();

    int hi = blockIdx.x * 8 + wid;
    float2 TH0 = THs[wid][0], TH1 = THs[wid][1];
    const float4* TL4 = reinterpret_cast<const float4*>(TL[hi & 1]);
    float4* sbase = st4 + (size_t)b * (DIM / 2) + hi * 128;
    float4 v[4];
    #pragma unroll
    for (int r = 0; r < 4; r++) v[r] = sbase[r * 32 + lane];
    // combined diagonal
    #pragma unroll
    for (int r = 0; r < 4; r++) {
        float4 dd = TL4[r * 32 + lane];
        float2 d0 = cmul(TH0, make_float2(dd.x, dd.y));
        float2 d1 = cmul(TH1, make_float2(dd.z, dd.w));
        float2 A = cmul(make_float2(v[r].x, v[r].y), d0);
        float2 B = cmul(make_float2(v[r].z, v[r].w), d1);
        v[r] = make_float4(A.x, A.y, B.x, B.y);
    }
    // bit0 gate (intra-float4)
    {
        float c = gcs[0].x, s = gcs[0].y;
        #pragma unroll
        for (int r = 0; r < 4; r++) {
            float4 a = v[r];
            v[r] = make_float4(c * a.x - s * a.z, c * a.y - s * a.w,
                               s * a.x + c * a.z, s * a.y + c * a.w);
        }
    }
    // bits 1..5: lane shuffles
    #pragma unroll
    for (int p = 1; p <= 5; p++) {
        float2 cp = gcs[p];
        float c = cp.x;
        float s = ((lane >> (p - 1)) & 1) ? cp.y : -cp.y;
        int msk = 1 << (p - 1);
        #pragma unroll
        for (int r = 0; r < 4; r++) {
            float px = __shfl_xor_sync(0xffffffffu, v[r].x, msk);
            float py = __shfl_xor_sync(0xffffffffu, v[r].y, msk);
            float pz = __shfl_xor_sync(0xffffffffu, v[r].z, msk);
            float pw = __shfl_xor_sync(0xffffffffu, v[r].w, msk);
            v[r].x = c * v[r].x + s * px;
            v[r].y = c * v[r].y + s * py;
            v[r].z = c * v[r].z + s * pz;
            v[r].w = c * v[r].w + s * pw;
        }
    }
    // bits 6..7: register butterflies
    #pragma unroll
    for (int pb = 0; pb < 2; pb++) {
        int m = 1 << pb;
        float2 cp = gcs[6 + pb];
        float c = cp.x, s = cp.y;
        #pragma unroll
        for (int r = 0; r < 4; r++)
            if (!(r & m)) {
                float4 A = v[r], B = v[r + m];
                v[r]     = make_float4(c * A.x - s * B.x, c * A.y - s * B.y,
                                       c * A.z - s * B.z, c * A.w - s * B.w);
                v[r + m] = make_float4(s * A.x + c * B.x, s * A.y + c * B.y,
                                       s * A.z + c * B.z, s * A.w + c * B.w);
            }
    }
    #pragma unroll
    for (int r = 0; r < 4; r++) sbase[r * 32 + lane] = v[r];
}

// ---------------------------------------------------------------------------
// KB: real rotations on j-bits 8..15 via conflict-free XOR-swizzled smem tile
// (tile index = lo*256 + (hi^lo)). Non-final: fused CNOT scatter with GF(2)-
// strength-reduced addressing. FINAL: fused signed-marginal readout.
template <bool FINAL>
__global__ __launch_bounds__(256)
void k_high(int layer, const float2* __restrict__ in,
            float2* __restrict__ outst, float* __restrict__ part) {
    int b = blockIdx.y, logrp = blockIdx.x;
    int tid = threadIdx.x, wid = tid >> 5, lane = tid & 31;
    __shared__ float2 gcs[8];
    __shared__ __align__(16) float2 tile[4096];   // [lo][hi^lo], 32 KB

    if (tid < 8) gcs[tid] = g_cs[(b * 4 + layer) * 16 + 8 + tid];

    int c   = wid * 2 + (lane >> 4);      // hi low nibble
    int lo4 = lane & 15;                  // lo low nibble
    int tbase = lo4 * 256 + (c ^ lo4);    // swizzled tile base (hi = it*16 + c)
    const float2* gbase = in + (size_t)b * DIM + logrp * 16 + c * 256 + lo4;
    #pragma unroll
    for (int it = 0; it < 16; it++)
        tile[tbase + (it << 4)] = gbase[it * 4096];
    __syncthreads();

    if (!FINAL) {
        #pragma unroll
        for (int sub = 0; sub < 2; sub++) {
            int lo = wid * 2 + sub;
            int gb = lo * 256 + (lane ^ lo);
            float2 v[8];
            #pragma unroll
            for (int r = 0; r < 8; r++) v[r] = tile[gb + r * 32];
            apply8_real(v, gcs, lane);
            #pragma unroll
            for (int r = 0; r < 8; r++) tile[gb + r * 32] = v[r];
        }
        __syncthreads();
        // scatter: j = sigma(ibase) ^ sigma(it<<12); second term constant-folds.
        int jbase = sigma16((c << 8) | (logrp << 4) | lo4);
        float2* obase = outst + (size_t)b * DIM;
        #pragma unroll
        for (int it = 0; it < 16; it++)
            obase[jbase ^ sigma16(it << 12)] = tile[tbase + (it << 4)];
    } else {
        float pa[8], spv[8], smv[8];
        #pragma unroll
        for (int sub = 0; sub < 2; sub++) {
            int lo = wid * 2 + sub;
            int gb = lo * 256 + (lane ^ lo);
            float2 v[8];
            #pragma unroll
            for (int r = 0; r < 8; r++) v[r] = tile[gb + r * 32];
            apply8_real(v, gcs, lane);
            if (sub == 0) {
                #pragma unroll
                for (int r = 0; r < 8; r++)
                    pa[r] = v[r].x * v[r].x + v[r].y * v[r].y;
            } else {
                #pragma unroll
                for (int r = 0; r < 8; r++) {
                    float pb = v[r].x * v[r].x + v[r].y * v[r].y;
                    spv[r] = pa[r] + pb;
                    smv[r] = pa[r] - pb;
                }
            }
        }
        __syncthreads();
        float* S  = (float*)tile;                 // [0..4095]
        float* S2 = (float*)tile + 4096;          // warpRed/R scratch
        #pragma unroll
        for (int r = 0; r < 8; r++) {
            S[wid * 256 + r * 32 + lane]        = spv[r];
            S[2048 + wid * 256 + r * 32 + lane] = smv[r];
        }
        __syncthreads();

        float V0 = 0.f, V1 = 0.f, V2 = 0.f, V3 = 0.f, V4 = 0.f;
        #pragma unroll
        for (int w2 = 0; w2 < 8; w2++) {
            float sp = S[w2 * 256 + tid];
            float sm = S[2048 + w2 * 256 + tid];
            int pw  = __popc(w2) & 1;
            int pw2 = __popc(w2 >> 1) & 1;
            int pw3 = (w2 >> 2) & 1;
            V4 += sp;
            V1 += pw  ? -sp : sp;
            V2 += pw2 ? -sp : sp;
            V3 += pw3 ? -sp : sp;
            V0 += pw  ? -sm : sm;
        }
        float A[12];
        int t = tid;
        int pf = __popc(t) & 1;
        #pragma unroll
        for (int k = 0; k < 7; k++)
            A[k] = (__popc(t >> k) & 1) ? -V4 : V4;
        A[7]  = pf ? -V0 : V0;
        A[8]  = pf ? -V1 : V1;
        A[9]  = pf ? -V2 : V2;
        A[10] = pf ? -V3 : V3;
        A[11] = (__popc(t & 0x7F) & 1) ? -V0 : V0;
        #pragma unroll
        for (int k = 0; k < 12; k++) {
            float a = A[k];
            #pragma unroll
            for (int o = 16; o; o >>= 1) a += __shfl_down_sync(0xffffffffu, a, o);
            if (lane == 0) S2[wid * 12 + k] = a;
        }
        __syncthreads();
        if (tid < 12) {
            float s = 0.f;
            #pragma unroll
            for (int w2 = 0; w2 < 8; w2++) s += S2[w2 * 12 + tid];
            S2[96 + tid] = s;
        }
        __syncthreads();
        if (tid < 16) {
            const float* R = S2 + 96;
            int q = tid, lg = logrp;
            float sgnAll = (__popc(lg) & 1) ? -1.f : 1.f;
            float val;
            if (q == 0)        val = sgnAll * R[11];
            else if (q < 8)    val = R[7 - q];
            else if (q < 12) {
                int P = 15 - q;
                val = ((__popc(lg >> (P - 4)) & 1) ? -1.f : 1.f) * R[0];
            } else {
                int P = 15 - q;
                val = sgnAll * R[7 + P];
            }
            part[(b * 16 + lg) * 16 + q] = val;
        }
    }
}

// Final deterministic reduction of partials -> out[b][q]
__global__ __launch_bounds__(256)
void k_reduce(const float* __restrict__ part, float* __restrict__ out) {
    int idx = blockIdx.x * 256 + threadIdx.x;
    int b = idx >> 4, q = idx & 15;
    float s = 0.f;
    #pragma unroll
    for (int gp = 0; gp < 16; gp++) s += part[(b * 16 + gp) * 16 + q];
    out[idx] = s;
}

// ---------------------------------------------------------------------------
extern "C" void kernel_launch(void* const* d_in, const int* in_sizes, int n_in,
                              void* d_out, int out_size) {
    const float* x = (const float*)d_in[0];
    const float* w = (const float*)d_in[1];
    if (n_in >= 2 && in_sizes[0] == 192) { const float* t = x; x = w; w = t; }
    float* out = (float*)d_out;

    float4 *s0, *s1; float* part;
    cudaGetSymbolAddress((void**)&s0, g_state0);
    cudaGetSymbolAddress((void**)&s1, g_state1);
    cudaGetSymbolAddress((void**)&part, g_partial);

    k_init<<<BATCH, 256>>>(x, w, s0);

    k_low <<<dim3(32, BATCH), 256>>>(1, s0);
    k_high<false><<<dim3(16, BATCH), 256>>>(1, (const float2*)s0, (float2*)s1, nullptr);

    k_low <<<dim3(32, BATCH), 256>>>(2, s1);
    k_high<false><<<dim3(16, BATCH), 256>>>(2, (const float2*)s1, (float2*)s0, nullptr);

    k_low <<<dim3(32, BATCH), 256>>>(3, s0);
    k_high<true> <<<dim3(16, BATCH), 256>>>(3, (const float2*)s0, nullptr, part);

    k_reduce<<<8, 256>>>(part, out);
}